// round 17
// baseline (speedup 1.0000x reference)
#include <cuda_runtime.h>
#include <cuda_fp16.h>
#include <cstdint>

// ---------------------------------------------------------------------------
// Experts MoE, fp16 mma.sync m16n8k16, fp32 accum (compute_103-safe).
// Round 17: PERSISTENT CTAs (304 = 2/SM) with seamless cross-tile mbarrier
// pipeline (R13 inner machinery) + dynamic work-stealing (atomic counter,
// reset each replay in the cvt kernel; thread0 fetches next tile at kt==0 and
// broadcasts via smem+mbarrier, consumed at kt==NT-2 with ~28 iters slack).
// W2 convert = work items 0..63 of gemm1's counter. X/W1 convert fused.
// ---------------------------------------------------------------------------

#define NEXPERTS 8
#define TOK_E    2048
#define HID      2048
#define FFN      1408
#define FFN2     2816

#define TILE_B 16384
#define STG    (2 * TILE_B)             // 32768
#define MBAR_OFF (3 * STG)
#define SMEM_TOTAL (3 * STG + 128)      // 98432 -> 2 CTAs/SM

#define NCTA    304
#define NT1     32
#define NTILES1 2816                    // 22 x 16 x 8
#define NT2     22
#define NTILES2 2048                    // 16 x 16 x 8
#define W2_F4_PER_CTA 90112             // (8*1408*2048/4)/64

__device__ __half g_Xh [(size_t)TOK_E * NEXPERTS * HID];
__device__ __half g_W1h[(size_t)NEXPERTS * HID * FFN2];    // [e][k][n] fp16
__device__ __half g_W2h[(size_t)NEXPERTS * FFN * HID];     // [e][k][n] fp16
__device__ __half g_act[(size_t)NEXPERTS * TOK_E * FFN];
__device__ int    g_ctr1;
__device__ int    g_ctr2;

__device__ __forceinline__ uint32_t s2u(const void* p) {
    uint32_t a;
    asm("{ .reg .u64 t; cvta.to.shared.u64 t, %1; cvt.u32.u64 %0, t; }" : "=r"(a) : "l"(p));
    return a;
}
__device__ __forceinline__ void cpa16(uint32_t s, const void* g) {
    asm volatile("cp.async.cg.shared.global [%0], [%1], 16;" :: "r"(s), "l"(g));
}
__device__ __forceinline__ void mbar_init(uint32_t a, uint32_t n) {
    asm volatile("mbarrier.init.shared.b64 [%0], %1;" :: "r"(a), "r"(n) : "memory");
}
__device__ __forceinline__ void cpa_arrive(uint32_t a) {
    asm volatile("cp.async.mbarrier.arrive.noinc.shared.b64 [%0];" :: "r"(a) : "memory");
}
__device__ __forceinline__ void mbar_arrive(uint32_t a) {
    asm volatile("mbarrier.arrive.shared.b64 _, [%0];" :: "r"(a) : "memory");
}
__device__ __forceinline__ void mbar_wait(uint32_t a, uint32_t ph) {
    uint32_t done;
    asm volatile(
        "{ .reg .pred p; mbarrier.try_wait.parity.acquire.cta.shared::cta.b64 p, [%1], %2; selp.b32 %0,1,0,p; }"
        : "=r"(done) : "r"(a), "r"(ph) : "memory");
    if (!done) {
        asm volatile(
            "{ .reg .pred P1;\nW_%=:\n mbarrier.try_wait.parity.acquire.cta.shared::cta.b64 P1, [%0], %1, 0x989680;\n @P1 bra.uni D_%=;\n bra.uni W_%=;\nD_%=:\n}"
            :: "r"(a), "r"(ph) : "memory");
    }
}
__device__ __forceinline__ void ldsm4(uint32_t* r, uint32_t addr) {
    asm volatile("ldmatrix.sync.aligned.m8n8.x4.shared.b16 {%0,%1,%2,%3}, [%4];"
                 : "=r"(r[0]), "=r"(r[1]), "=r"(r[2]), "=r"(r[3]) : "r"(addr));
}
__device__ __forceinline__ void ldsm4t(uint32_t* r, uint32_t addr) {
    asm volatile("ldmatrix.sync.aligned.m8n8.x4.trans.shared.b16 {%0,%1,%2,%3}, [%4];"
                 : "=r"(r[0]), "=r"(r[1]), "=r"(r[2]), "=r"(r[3]) : "r"(addr));
}
__device__ __forceinline__ void mma16(float d[4], const uint32_t a[4], uint32_t b0, uint32_t b1) {
    asm volatile(
        "mma.sync.aligned.m16n8k16.row.col.f32.f16.f16.f32 "
        "{%0,%1,%2,%3}, {%4,%5,%6,%7}, {%8,%9}, {%0,%1,%2,%3};\n"
        : "+f"(d[0]), "+f"(d[1]), "+f"(d[2]), "+f"(d[3])
        : "r"(a[0]), "r"(a[1]), "r"(a[2]), "r"(a[3]), "r"(b0), "r"(b1));
}
__device__ __forceinline__ float silu(float x) { return x / (1.0f + __expf(-x)); }

__device__ __forceinline__ uint2 cvt4h(float4 v) {
    __half2 h0 = __floats2half2_rn(v.x, v.y);
    __half2 h1 = __floats2half2_rn(v.z, v.w);
    uint2 u;
    u.x = *reinterpret_cast<uint32_t*>(&h0);
    u.y = *reinterpret_cast<uint32_t*>(&h1);
    return u;
}

// ===========================================================================
// Fused streaming f32 -> fp16 convert for X and W1; also resets work counters.
// ===========================================================================
__global__ __launch_bounds__(256)
void cvt_fused_kernel(const float* __restrict__ X, const float* __restrict__ W1,
                      __half* __restrict__ xh, __half* __restrict__ w1h,
                      size_t nX4, size_t nTot4) {
    if (blockIdx.x == 0 && threadIdx.x == 0) { g_ctr1 = 0; g_ctr2 = 0; }
    for (size_t i = (size_t)blockIdx.x * blockDim.x + threadIdx.x; i < nTot4;
         i += (size_t)gridDim.x * blockDim.x) {
        if (i < nX4) {
            reinterpret_cast<uint2*>(xh)[i] =
                cvt4h(reinterpret_cast<const float4*>(X)[i]);
        } else {
            const size_t j = i - nX4;
            reinterpret_cast<uint2*>(w1h)[j] =
                cvt4h(reinterpret_cast<const float4*>(W1)[j]);
        }
    }
}

// ===========================================================================
// Pipelined compute for one BK=64 stage (A hoisted, B ping-pong) — R13 proven.
// ===========================================================================
#define COMPUTE_STAGE(sa, sB)                                                   \
    {                                                                           \
        uint32_t afr[4][2][4];                                                  \
        _Pragma("unroll")                                                       \
        for (int ks = 0; ks < 4; ks++)                                          \
            _Pragma("unroll")                                                   \
            for (int mt = 0; mt < 2; mt++)                                      \
                ldsm4(afr[ks][mt],                                              \
                      (sa) + aRow[mt] + ((((uint32_t)(2 * ks) + hiA) ^ aS[mt]) << 4)); \
        uint32_t bf[2][4];                                                      \
        ldsm4t(bf[0], (sB) + rowB + swB[0]);                                    \
        _Pragma("unroll")                                                       \
        for (int s = 0; s < 16; s++) {                                          \
            const int ks = s >> 2, nq = s & 3;                                  \
            const int cur = s & 1, nxt = cur ^ 1;                               \
            if (s < 15) {                                                       \
                const int s1 = s + 1;                                           \
                ldsm4t(bf[nxt], (sB) + (uint32_t)((s1 >> 2) * 4096) + rowB + swB[s1 & 3]); \
            }                                                                   \
            mma16(acc[0][nq * 2 + 0], afr[ks][0], bf[cur][0], bf[cur][1]);      \
            mma16(acc[1][nq * 2 + 0], afr[ks][1], bf[cur][0], bf[cur][1]);      \
            mma16(acc[0][nq * 2 + 1], afr[ks][0], bf[cur][2], bf[cur][3]);      \
            mma16(acc[1][nq * 2 + 1], afr[ks][1], bf[cur][2], bf[cur][3]);      \
        }                                                                       \
    }

// smem control block layout (after tiles): full[3] @ +0, empty[3] @ +24,
// tileReady[2] @ +48, tile-id ints @ +64.
#define MBAR_SETUP()                                                            \
    const uint32_t mbF  = sb + MBAR_OFF;                                        \
    const uint32_t mbE  = sb + MBAR_OFF + 24;                                   \
    const uint32_t tRdy = sb + MBAR_OFF + 48;                                   \
    volatile int* sTl = reinterpret_cast<volatile int*>(smem + MBAR_OFF + 64);  \
    if (tid == 0) {                                                             \
        for (int s = 0; s < 3; s++) { mbar_init(mbF + s * 8, 256); mbar_init(mbE + s * 8, 256); } \
        mbar_init(tRdy, 1); mbar_init(tRdy + 8, 1);                             \
    }                                                                           \
    __syncthreads();

// Persistent seamless pipeline: tiles fetched dynamically, pipeline never
// drains across tile boundaries. thread0 fetches tile n+1 at tile n kt==0
// (broadcast via sTl + tRdy); all threads adopt it at kt==NT-2.
#define PERSIST_LOOP(NT, NTILES, CTR, OFS)                                      \
    setProd(curTile);                                                           \
    issueKt(0, 0); cpa_arrive(mbF + 0);                                         \
    issueKt(1, 1); cpa_arrive(mbF + 8);                                         \
    int fetchN = 0, g = 0, nextTile = 0; bool haveNext = false;                 \
    for (;;) {                                                                  \
        for (int kt = 0; kt < (NT); kt++, g++) {                                \
            const uint32_t st = (uint32_t)(g % 3);                              \
            if (kt == 0 && tid == 0) {                                          \
                const int f = fetchN + 1;                                       \
                sTl[f & 1] = atomicAdd(&CTR, 1) - (OFS);                        \
                mbar_arrive(tRdy + (uint32_t)(f & 1) * 8);                      \
            }                                                                   \
            mbar_wait(mbF + st * 8, (uint32_t)((g / 3) & 1));                   \
            {                                                                   \
                const uint32_t sa = sb + st * STG;                              \
                const uint32_t sB = sa + TILE_B;                                \
                COMPUTE_STAGE(sa, sB)                                           \
            }                                                                   \
            mbar_arrive(mbE + st * 8);                                          \
            const int jkt = kt + 2;                                             \
            const int jg = g + 2;                                               \
            if (jkt == (NT)) {                                                  \
                const int f = fetchN + 1;                                       \
                mbar_wait(tRdy + (uint32_t)(f & 1) * 8, (uint32_t)(((f - 1) >> 1) & 1)); \
                nextTile = sTl[f & 1];                                          \
                haveNext = (nextTile >= 0) && (nextTile < (NTILES));            \
                if (haveNext) setProd(nextTile);                                \
            }                                                                   \
            if ((jkt < (NT)) || haveNext) {                                     \
                const uint32_t s2 = (uint32_t)(jg % 3);                         \
                if (jg >= 3) mbar_wait(mbE + s2 * 8, (uint32_t)(((jg / 3) + 1) & 1)); \
                issueKt(jkt < (NT) ? jkt : jkt - (NT), s2);                     \
                cpa_arrive(mbF + s2 * 8);                                       \
            }                                                                   \
        }                                                                       \
        epilogueTile(curTile);                                                  \
        fetchN++;                                                               \
        if (!haveNext) break;                                                   \
        curTile = nextTile;                                                     \
    }

// ===========================================================================
// GEMM1 + swiglu, persistent. Work items: 0..63 = W2 cvt chunks,
// 64.. = GEMM tiles (t -> e = t/352, mt = (t%352)/22, nt = t%22).
// B stage n-cols: [a(0:32) | b(0:32) | a(32:64) | b(32:64)] (k-major rows).
// ===========================================================================
__global__ __launch_bounds__(256, 2)
void gemm1_kernel(const float* __restrict__ W2src) {
    const int tid = threadIdx.x, warp = tid >> 5, lane = tid & 31;
    const int wm = warp >> 1, wn = warp & 1;
    extern __shared__ char smem[];
    const uint32_t sb = s2u(smem);

    // ---- tile-independent producer bases ----
    const int pr = tid >> 3, kc = tid & 7;
    const uint32_t swcA = (uint32_t)((kc ^ (pr & 7)) << 4);
    uint32_t dOffA[4];
    const __half* aC[4];
    #pragma unroll
    for (int i = 0; i < 4; i++) {
        dOffA[i] = (uint32_t)((pr + 32 * i) * 128) + swcA;
        aC[i] = g_Xh + (size_t)(pr + 32 * i) * HID + kc * 8;
    }
    const int rB = tid >> 3, cB = tid & 7;
    uint32_t dOffB[4];
    const __half* bC[4];
    #pragma unroll
    for (int j = 0; j < 4; j++) {
        const int row = rB + (j >> 1) * 32;
        const int ch  = cB + (j & 1) * 8;
        const int gr  = ch >> 2;
        const int colC = (gr >> 1) * 32 + (ch & 3) * 8 + ((gr & 1) ? FFN : 0);
        dOffB[j] = (uint32_t)(row * 256 + ((ch ^ (rB & 7)) << 4));
        bC[j] = g_W1h + (size_t)row * FFN2 + colC;
    }
    // ---- consumer fragment addressing ----
    const uint32_t hiA = lane >> 4;
    uint32_t aRow[2], aS[2];
    #pragma unroll
    for (int mt = 0; mt < 2; mt++) {
        const int r = wm * 32 + mt * 16 + (lane & 15);
        aRow[mt] = (uint32_t)(r * 128); aS[mt] = (uint32_t)(r & 7);
    }
    const uint32_t rowB = (uint32_t)((((lane >> 3) & 1) * 8 + (lane & 7)) * 256);
    uint32_t swB[4];
    #pragma unroll
    for (int nq = 0; nq < 4; nq++)
        swB[nq] = (uint32_t)((((wn * 8 + nq * 2 + (lane >> 4)) ^ (lane & 7))) << 4);

    float acc[2][8][4] = {};

    MBAR_SETUP()

    // ---- draw initial items; cvt chunks first ----
    int item;
    for (;;) {
        if (tid == 0) sTl[0] = atomicAdd(&g_ctr1, 1);
        __syncthreads();
        item = sTl[0];
        __syncthreads();
        if (item >= 64) break;
        const float4* s4 = reinterpret_cast<const float4*>(W2src) + (size_t)item * W2_F4_PER_CTA;
        uint2* d4 = reinterpret_cast<uint2*>(g_W2h) + (size_t)item * W2_F4_PER_CTA;
        #pragma unroll 4
        for (int i = tid; i < W2_F4_PER_CTA; i += 256)
            d4[i] = cvt4h(s4[i]);
    }
    int curTile = item - 64;
    if (curTile >= NTILES1) return;

    size_t aOff = 0, bOff = 0;
    auto setProd = [&](int t) {
        const int e = t / 352, rem = t % 352, mt = rem / 22, nt = rem % 22;
        aOff = (size_t)(e * TOK_E + mt * 128) * HID;
        bOff = (size_t)e * HID * FFN2 + (size_t)nt * 64;
    };
    auto issueKt = [&](int kt, uint32_t st) {
        const uint32_t s  = sb + st * STG;
        const uint32_t sB2 = s + TILE_B;
        #pragma unroll
        for (int i = 0; i < 4; i++) cpa16(s + dOffA[i], aC[i] + aOff + (size_t)kt * 64);
        #pragma unroll
        for (int j = 0; j < 4; j++) cpa16(sB2 + dOffB[j], bC[j] + bOff + (size_t)kt * (64 * FFN2));
    };
    const int lg = lane >> 2, lt = lane & 3;
    auto epilogueTile = [&](int t) {
        const int e = t / 352, rem = t % 352, mt0 = rem / 22, nt = rem % 22;
        __half* actBase = g_act + ((size_t)(e * TOK_E + mt0 * 128)) * FFN + nt * 64 + wn * 32;
        #pragma unroll
        for (int mt = 0; mt < 2; mt++) {
            #pragma unroll
            for (int j = 0; j < 4; j++) {
                const int r = wm * 32 + mt * 16 + lg;
                const int c = 8 * j + 2 * lt;
                const float* pa = acc[mt][j];
                const float* pb = acc[mt][4 + j];
                __half2 v0 = __floats2half2_rn(silu(pa[0]) * pb[0], silu(pa[1]) * pb[1]);
                __half2 v1 = __floats2half2_rn(silu(pa[2]) * pb[2], silu(pa[3]) * pb[3]);
                *reinterpret_cast<__half2*>(actBase + (size_t)r * FFN + c)       = v0;
                *reinterpret_cast<__half2*>(actBase + (size_t)(r + 8) * FFN + c) = v1;
            }
        }
        #pragma unroll
        for (int a = 0; a < 2; a++)
            #pragma unroll
            for (int b = 0; b < 8; b++)
                #pragma unroll
                for (int c = 0; c < 4; c++) acc[a][b][c] = 0.0f;
    };

    PERSIST_LOOP(NT1, NTILES1, g_ctr1, 64)
}

// ===========================================================================
// GEMM2 persistent: tiles t -> e = t/256, mt = (t%256)/16, nt = t%16.
// ===========================================================================
__global__ __launch_bounds__(256, 2)
void gemm2_kernel(float* __restrict__ out) {
    const int tid = threadIdx.x, warp = tid >> 5, lane = tid & 31;
    const int wm = warp >> 1, wn = warp & 1;
    extern __shared__ char smem[];
    const uint32_t sb = s2u(smem);

    const int pr = tid >> 3, kc = tid & 7;
    const uint32_t swcA = (uint32_t)((kc ^ (pr & 7)) << 4);
    uint32_t dOffA[4];
    const __half* aC[4];
    #pragma unroll
    for (int i = 0; i < 4; i++) {
        dOffA[i] = (uint32_t)((pr + 32 * i) * 128) + swcA;
        aC[i] = g_act + (size_t)(pr + 32 * i) * FFN + kc * 8;
    }
    const int rB = tid >> 3, cB = tid & 7;
    uint32_t dOffB[4];
    const __half* bC[4];
    #pragma unroll
    for (int j = 0; j < 4; j++) {
        const int row = rB + (j >> 1) * 32;
        const int ch  = cB + (j & 1) * 8;
        dOffB[j] = (uint32_t)(row * 256 + ((ch ^ (rB & 7)) << 4));
        bC[j] = g_W2h + (size_t)row * HID + ch * 8;
    }
    const uint32_t hiA = lane >> 4;
    uint32_t aRow[2], aS[2];
    #pragma unroll
    for (int mt = 0; mt < 2; mt++) {
        const int r = wm * 32 + mt * 16 + (lane & 15);
        aRow[mt] = (uint32_t)(r * 128); aS[mt] = (uint32_t)(r & 7);
    }
    const uint32_t rowB = (uint32_t)((((lane >> 3) & 1) * 8 + (lane & 7)) * 256);
    uint32_t swB[4];
    #pragma unroll
    for (int nq = 0; nq < 4; nq++)
        swB[nq] = (uint32_t)((((wn * 8 + nq * 2 + (lane >> 4)) ^ (lane & 7))) << 4);

    float acc[2][8][4] = {};

    MBAR_SETUP()

    if (tid == 0) sTl[0] = atomicAdd(&g_ctr2, 1);
    __syncthreads();
    int curTile = sTl[0];
    if (curTile >= NTILES2) return;

    size_t aOff = 0, bOff = 0;
    auto setProd = [&](int t) {
        const int e = t / 256, rem = t % 256, mt = rem / 16, nt = rem % 16;
        aOff = (size_t)(e * TOK_E + mt * 128) * FFN;
        bOff = (size_t)e * FFN * HID + (size_t)nt * 128;
    };
    auto issueKt = [&](int kt, uint32_t st) {
        const uint32_t s  = sb + st * STG;
        const uint32_t sB2 = s + TILE_B;
        #pragma unroll
        for (int i = 0; i < 4; i++) cpa16(s + dOffA[i], aC[i] + aOff + (size_t)kt * 64);
        #pragma unroll
        for (int j = 0; j < 4; j++) cpa16(sB2 + dOffB[j], bC[j] + bOff + (size_t)kt * (64 * HID));
    };
    const int lg = lane >> 2, lt = lane & 3;
    auto epilogueTile = [&](int t) {
        const int e = t / 256, rem = t % 256, mt0 = rem / 16, nt = rem % 16;
        float* outBase = out + ((size_t)(e * TOK_E + mt0 * 128)) * HID + nt * 128 + wn * 64;
        #pragma unroll
        for (int mt = 0; mt < 2; mt++) {
            #pragma unroll
            for (int j = 0; j < 8; j++) {
                const int r = wm * 32 + mt * 16 + lg;
                const int c = 8 * j + 2 * lt;
                const float* d = acc[mt][j];
                *reinterpret_cast<float2*>(outBase + (size_t)r * HID + c)       = make_float2(d[0], d[1]);
                *reinterpret_cast<float2*>(outBase + (size_t)(r + 8) * HID + c) = make_float2(d[2], d[3]);
            }
        }
        #pragma unroll
        for (int a = 0; a < 2; a++)
            #pragma unroll
            for (int b = 0; b < 8; b++)
                #pragma unroll
                for (int c = 0; c < 4; c++) acc[a][b][c] = 0.0f;
    };

    PERSIST_LOOP(NT2, NTILES2, g_ctr2, 0)
}

// ===========================================================================
// Launch
// ===========================================================================
extern "C" void kernel_launch(void* const* d_in, const int* in_sizes, int n_in,
                              void* d_out, int out_size) {
    const float* X  = (const float*)d_in[0];
    const float* W1 = (const float*)d_in[2];
    const float* W2 = (const float*)d_in[3];
    float* out = (float*)d_out;

    __half* xh;  cudaGetSymbolAddress((void**)&xh,  g_Xh);
    __half* w1h; cudaGetSymbolAddress((void**)&w1h, g_W1h);

    cudaFuncSetAttribute(gemm1_kernel, cudaFuncAttributeMaxDynamicSharedMemorySize, SMEM_TOTAL);
    cudaFuncSetAttribute(gemm2_kernel, cudaFuncAttributeMaxDynamicSharedMemorySize, SMEM_TOTAL);

    const size_t nX4 = (size_t)TOK_E * NEXPERTS * HID / 4;
    const size_t nW4 = (size_t)NEXPERTS * HID * FFN2 / 4;
    cvt_fused_kernel<<<4096, 256>>>(X, W1, xh, w1h, nX4, nX4 + nW4);

    gemm1_kernel<<<NCTA, 256, SMEM_TOTAL>>>(W2);
    gemm2_kernel<<<NCTA, 256, SMEM_TOTAL>>>(out);
}